// round 16
// baseline (speedup 1.0000x reference)
#include <cuda_runtime.h>
#include <cuda_fp16.h>
#include <cstdint>

#define H 128
#define W 128
#define OH 64
#define OW 64
#define TAPS 6
#define NTHREADS 256
#define NWARPS 8
#define NCHAN 4096

// Byte layout (56,624 B => 4 CTAs/SM):
//   0      xs2       fp16 tile            32768
//   32768  tmp16     fp16 [64][136]       17408  (4+128+4 guard halfs/row)
//   50176  wtabP5h8  P5 half2 wts 64x8    2048   (pair-window aligned, {w,w})
//   52224  wtab8     P6 f32 wts 64x8      2048   (window-aligned)
//   54272  pairRow   32 pairs x 8 ints    1024   (clamped uint2-row offsets)
//   55296  word0tab  64 ints              256
//   55552  rowMinOrd u32[128]             512
//   56064  rowMaxOrd u32[128]             512
//   56576  misc                           48
// Aliased on tmp16 (dead before P5): partMin f32[1024], partMax f32[1024],
//   colMin f32[128], colMax f32[128]
#define SMEM_BYTES 56624

__device__ __forceinline__ unsigned f2ord(float f) {
    int b = __float_as_int(f);
    return (unsigned)b ^ ((b < 0) ? 0xFFFFFFFFu : 0x80000000u);
}
__device__ __forceinline__ float ord2f(unsigned u) {
    int b = (int)(u ^ ((u & 0x80000000u) ? 0x80000000u : 0xFFFFFFFFu));
    return __int_as_float(b);
}
__device__ __forceinline__ unsigned warp_min_u32(unsigned v) {
    unsigned r; asm("redux.sync.min.u32 %0, %1, 0xffffffff;" : "=r"(r) : "r"(v)); return r;
}
__device__ __forceinline__ unsigned warp_max_u32(unsigned v) {
    unsigned r; asm("redux.sync.max.u32 %0, %1, 0xffffffff;" : "=r"(r) : "r"(v)); return r;
}
__device__ __forceinline__ int warp_max_s32(int v) {
    int r; asm("redux.sync.max.s32 %0, %1, 0xffffffff;" : "=r"(r) : "r"(v)); return r;
}

__global__ void __launch_bounds__(NTHREADS, 4)
smartpool_kernel(const float* __restrict__ x, float* __restrict__ out, int NC)
{
    extern __shared__ char smc[];
    uint2*    xs2      = (uint2*)smc;                   // 128 rows x 32 uint2
    __half*   tmp16    = (__half*)(smc + 32768);        // [64][136]
    unsigned* wtabP5h8 = (unsigned*)(smc + 50176);      // [64][8] packed half2
    float*    wtab8    = (float*)(smc + 52224);         // [64][8]
    int*      pairRow  = (int*)(smc + 54272);           // [32][8]
    int*      word0tab = (int*)(smc + 55296);           // [64]
    unsigned* rowMinOrd= (unsigned*)(smc + 55552);      // [128]
    unsigned* rowMaxOrd= (unsigned*)(smc + 56064);      // [128]
    float*    misc     = (float*)(smc + 56576);
    unsigned* miscU    = (unsigned*)misc;
    float* partMin = (float*)tmp16;                     // aliases, dead before P5
    float* partMax = partMin + 1024;
    float* colMin  = partMin + 2048;
    float* colMax  = colMin + 128;

    const int tid  = threadIdx.x;
    const int lane = tid & 31;
    const int wi   = tid >> 5;
    const unsigned FULL = 0xFFFFFFFFu;
    const float FINF = 3.402823466e38f;

    for (int nc = blockIdx.x; nc < NC; nc += gridDim.x) {
        const float4* x4 = (const float4*)(x + (size_t)nc * (H * W));

        // ===== Phase 1: stream tile -> fp16 SMEM + fused row/col stats ======
        float4 cmn = {FINF, FINF, FINF, FINF};
        float4 cmx = {-FINF, -FINF, -FINF, -FINF};
        #pragma unroll 8
        for (int i = 0; i < 16; i++) {
            const int idx = tid + i * NTHREADS;
            const float4 v = x4[idx];
            __half2 h01 = __floats2half2_rn(v.x, v.y);
            __half2 h23 = __floats2half2_rn(v.z, v.w);
            uint2 pk;
            pk.x = *(const unsigned*)&h01;
            pk.y = *(const unsigned*)&h23;
            xs2[idx] = pk;
            cmn.x = fminf(cmn.x, v.x); cmn.y = fminf(cmn.y, v.y);
            cmn.z = fminf(cmn.z, v.z); cmn.w = fminf(cmn.w, v.w);
            cmx.x = fmaxf(cmx.x, v.x); cmx.y = fmaxf(cmx.y, v.y);
            cmx.z = fmaxf(cmx.z, v.z); cmx.w = fmaxf(cmx.w, v.w);
            float lmn = fminf(fminf(v.x, v.y), fminf(v.z, v.w));
            float lmx = fmaxf(fmaxf(v.x, v.y), fmaxf(v.z, v.w));
            unsigned omn = warp_min_u32(f2ord(lmn));
            unsigned omx = warp_max_u32(f2ord(lmx));
            if (lane == 0) {
                const int r = wi + 8 * i;
                rowMinOrd[r] = omn;
                rowMaxOrd[r] = omx;
            }
        }
        ((float4*)partMin)[wi * 32 + lane] = cmn;
        ((float4*)partMax)[wi * 32 + lane] = cmx;
        __syncthreads();

        // ===== Phase 2: finish stats =======================================
        if (tid < 128) {
            const int c = tid;
            float mn = partMin[c], mx = partMax[c];
            #pragma unroll
            for (int w = 1; w < 8; w++) {
                mn = fminf(mn, partMin[w * 128 + c]);
                mx = fmaxf(mx, partMax[w * 128 + c]);
            }
            colMin[c] = mn;
            colMax[c] = mx;
        } else if (wi == 4) {
            unsigned m = max(max(rowMaxOrd[lane], rowMaxOrd[lane + 32]),
                             max(rowMaxOrd[lane + 64], rowMaxOrd[lane + 96]));
            m = warp_max_u32(m);
            if (lane == 0) {
                const float thr = 0.1f * ord2f(m);
                misc[0]  = thr;
                miscU[1] = f2ord(thr);
            }
        }
        __syncthreads();

        // ===== Phase 3: bbox ===============================================
        if (wi == 0) {
            const unsigned thrO = miscU[1];
            bool orB = false; int mx = 0;
            #pragma unroll
            for (int k = lane; k < 128; k += 32) {
                if (k >= 1) {
                    if (rowMinOrd[k] <  thrO) orB = true;
                    if (rowMaxOrd[k] >= thrO) mx = max(mx, k);
                }
            }
            orB = __any_sync(FULL, orB);
            mx = warp_max_s32(mx);
            if (lane == 0) { misc[2] = orB ? 0.0f : 1.0f; misc[3] = (float)mx; }
        } else if (wi == 1) {
            const float thr = misc[0];
            bool orB = false; int mx = 0;
            #pragma unroll
            for (int k = lane; k < 128; k += 32) {
                if (k >= 1) {
                    if (colMin[k] <  thr) orB = true;
                    if (colMax[k] >= thr) mx = max(mx, k);
                }
            }
            orB = __any_sync(FULL, orB);
            mx = warp_max_s32(mx);
            if (lane == 0) { misc[4] = orB ? 0.0f : 1.0f; misc[5] = (float)mx; }
        }
        __syncthreads();

        // ===== Phase 4: window-aligned weight tables + guard zeroing =======
        if (tid < 128) {
            const int  isW = tid >> 6;
            const int  o   = tid & 63;
            const float lo = misc[2 + 2 * isW];
            const float hi = misc[3 + 2 * isW];
            const float L       = hi - lo + 1.0f;
            const float scale   = L * (1.0f / 64.0f);
            const float support = fmaxf(scale, 1.0f);
            const float a       = lo - 0.5f + scale * ((float)o + 0.5f);
            if (isW == 0) {
                // P5: 8-slot window shared by the (even,odd) output-row pair
                const int oe = o & ~1;
                const float aE = lo - 0.5f + scale * ((float)oe + 0.5f);
                const int jbase = (int)floorf(aE - support);   // pair window start
                float w8[8]; float ssum = 0.0f;
                #pragma unroll
                for (int k = 0; k < 8; k++) {
                    const float jf = (float)(jbase + k);
                    float wv = fmaxf(0.0f, 1.0f - fabsf(jf - a) / support);
                    wv = (jf >= lo && jf <= hi) ? wv : 0.0f;
                    w8[k] = wv; ssum += wv;
                }
                const float inv = 1.0f / fmaxf(ssum, 1e-12f);
                #pragma unroll
                for (int k = 0; k < 8; k++) {
                    const __half2 wh2 = __half2half2(__float2half_rn(w8[k] * inv));
                    wtabP5h8[o * 8 + k] = *(const unsigned*)&wh2;
                }
                if ((o & 1) == 0) {
                    #pragma unroll
                    for (int k = 0; k < 8; k++)
                        pairRow[(o >> 1) * 8 + k] = min(max(jbase + k, 0), 127) * 32;
                }
            } else {
                // P6: word-aligned 8-slot window (slot k <-> j = 2*word0+k-4)
                const int j0    = (int)floorf(a - support);     // in [-2,125]
                const int word0 = (j0 + 4) >> 1;                // in [1,64]
                const int jw    = 2 * word0 - 4;                // window start j
                float w8[8]; float ssum = 0.0f;
                #pragma unroll
                for (int k = 0; k < 8; k++) {
                    const float jf = (float)(jw + k);
                    float wv = fmaxf(0.0f, 1.0f - fabsf(jf - a) / support);
                    wv = (jf >= lo && jf <= hi) ? wv : 0.0f;
                    w8[k] = wv; ssum += wv;
                }
                const float inv = 1.0f / fmaxf(ssum, 1e-12f);
                #pragma unroll
                for (int k = 0; k < 8; k++) wtab8[o * 8 + k] = w8[k] * inv;
                word0tab[o] = word0;
            }
        } else {
            // zero the 4 guard words per tmp16 row (words 0,1,66,67 of 68)
            const int t = tid - 128;
            const int r = t >> 1;
            const int base = r * 68 + ((t & 1) ? 66 : 0);
            ((unsigned*)tmp16)[base]     = 0u;
            ((unsigned*)tmp16)[base + 1] = 0u;
        }
        __syncthreads();

        // ===== Phase 5: row resize, pair-shared 8-row window, HFMA2 =========
        // Warp handles 4 pairs (8 output rows). Full warp loads each of the
        // pair's 8 input rows once (LDS.64, lane = uint2 of 4 halfs), both
        // outputs accumulate with their own zero-padded half2 weights.
        {
            uint2* tmp2 = (uint2*)tmp16;           // row stride 34 uint2
            #pragma unroll
            for (int t = 0; t < 4; t++) {
                const int m  = wi * 4 + t;         // pair index 0..31
                const int o0 = 2 * m;
                const int4  rbA = ((const int4*)pairRow)[m * 2 + 0];
                const int4  rbB = ((const int4*)pairRow)[m * 2 + 1];
                const uint4 wEa = ((const uint4*)wtabP5h8)[o0 * 2 + 0];
                const uint4 wEb = ((const uint4*)wtabP5h8)[o0 * 2 + 1];
                const uint4 wOa = ((const uint4*)wtabP5h8)[o0 * 2 + 2];
                const uint4 wOb = ((const uint4*)wtabP5h8)[o0 * 2 + 3];
                __half2 ae0 = __float2half2_rn(0.0f);
                __half2 ae1 = ae0, ao0 = ae0, ao1 = ae0;
                #define P5_SLOT(rb, we_u, wo_u) do {                          \
                    const uint2 v = xs2[(rb) + lane];                         \
                    const __half2 vl = *(const __half2*)&v.x;                 \
                    const __half2 vh = *(const __half2*)&v.y;                 \
                    const __half2 we = *(const __half2*)&(we_u);              \
                    const __half2 wo = *(const __half2*)&(wo_u);              \
                    ae0 = __hfma2(vl, we, ae0); ae1 = __hfma2(vh, we, ae1);   \
                    ao0 = __hfma2(vl, wo, ao0); ao1 = __hfma2(vh, wo, ao1);   \
                } while (0)
                P5_SLOT(rbA.x, wEa.x, wOa.x);
                P5_SLOT(rbA.y, wEa.y, wOa.y);
                P5_SLOT(rbA.z, wEa.z, wOa.z);
                P5_SLOT(rbA.w, wEa.w, wOa.w);
                P5_SLOT(rbB.x, wEb.x, wOb.x);
                P5_SLOT(rbB.y, wEb.y, wOb.y);
                P5_SLOT(rbB.z, wEb.z, wOb.z);
                P5_SLOT(rbB.w, wEb.w, wOb.w);
                #undef P5_SLOT
                uint2 pe, po;
                pe.x = *(const unsigned*)&ae0;
                pe.y = *(const unsigned*)&ae1;
                po.x = *(const unsigned*)&ao0;
                po.y = *(const unsigned*)&ao1;
                tmp2[o0 * 34 + 1 + lane]       = pe;   // halfs 4+4*lane..
                tmp2[(o0 + 1) * 34 + 1 + lane] = po;
            }
        }
        __syncthreads();

        // ===== Phase 6: col resize from guarded fp16 tmp, 4xLDS.32 + 8 FMA ==
        {
            const int p  = tid & 63;
            const int og = tid >> 6;
            const unsigned* t32 = (const unsigned*)tmp16;
            float w8[8];
            #pragma unroll
            for (int k = 0; k < 8; k++) w8[k] = wtab8[p * 8 + k];
            const int word0 = word0tab[p];
            float* outc = out + (size_t)nc * (OH * OW);
            #pragma unroll 4
            for (int g = 0; g < 16; g++) {
                const int o = og * 16 + g;
                const int base = o * 68 + word0;
                const unsigned u0 = t32[base + 0];
                const unsigned u1 = t32[base + 1];
                const unsigned u2 = t32[base + 2];
                const unsigned u3 = t32[base + 3];
                const float2 f0 = __half22float2(*(const __half2*)&u0);
                const float2 f1 = __half22float2(*(const __half2*)&u1);
                const float2 f2 = __half22float2(*(const __half2*)&u2);
                const float2 f3 = __half22float2(*(const __half2*)&u3);
                float acc;
                acc =      w8[0] * f0.x;
                acc = fmaf(w8[1], f0.y, acc);
                acc = fmaf(w8[2], f1.x, acc);
                acc = fmaf(w8[3], f1.y, acc);
                acc = fmaf(w8[4], f2.x, acc);
                acc = fmaf(w8[5], f2.y, acc);
                acc = fmaf(w8[6], f3.x, acc);
                acc = fmaf(w8[7], f3.y, acc);
                outc[o * OW + p] = acc;
            }
        }
        __syncthreads();   // protect xs2 / tmp16 aliases for next channel
    }
}

extern "C" void kernel_launch(void* const* d_in, const int* in_sizes, int n_in,
                              void* d_out, int out_size)
{
    const float* x = (const float*)d_in[0];
    float* out = (float*)d_out;
    const int nc = in_sizes[0] / (H * W);   // 4096 channels
    int nsm = 148;
    cudaDeviceGetAttribute(&nsm, cudaDevAttrMultiProcessorCount, 0);
    int grid = nsm * 4;
    if (grid > nc) grid = nc;
    cudaFuncSetAttribute(smartpool_kernel,
                         cudaFuncAttributeMaxDynamicSharedMemorySize, SMEM_BYTES);
    smartpool_kernel<<<grid, NTHREADS, SMEM_BYTES>>>(x, out, nc);
}